// round 4
// baseline (speedup 1.0000x reference)
#include <cuda_runtime.h>

// CRF negative log-likelihood, T=512 B=64 L=48, START=46, STOP=47.
// Single fused kernel: buffer detection + gold score + forward recursion +
// last-block deterministic reduction.
//
// forward recursion in linear space with carried log offset (normalize by u[0]):
//   s_j   = sum_i u_{t-1}[i] * E[i][j],   E = exp(Tr)
//   u_t[j]= s_j * exp(f_t[j]-f_t[0]) / u_{t-1}[0]
//   C_t   = C_{t-1} + f_t[0] + ln u_{t-1}[0]
//
// Inputs resolved by evidence: feats/transitions by element count; tags vs
// mask (both 32768 elems) by byte content; tags dtype (i32/i64) and mask
// width (1B/4B) detected on-device.

#define TT 512
#define BB 64
#define LLAB 48
#define START_TAG 46
#define STOP_TAG 47
#define NT 96
#define L2E 1.4426950408889634f
#define LN2f 0.6931471805599453f
#define FSTRIDE (BB * LLAB)   // 3072 floats per time step
#define PFD 4                 // feats prefetch distance (ring size)

__device__ float        g_partial[BB];
__device__ unsigned int g_done;       // wraps 0..63 -> self-resetting per launch

__device__ __forceinline__ int get_tag(const void* tags, int idx, int is32) {
    int v = is32 ? ((const int*)tags)[idx]
                 : (int)((const long long*)tags)[idx];
    return v < 0 ? 0 : (v > 47 ? 47 : v);      // clamp: OOB-proof
}
__device__ __forceinline__ int get_mask(const void* mask, int idx, int is8) {
    return is8 ? (int)((const unsigned char*)mask)[idx]
               : (((const int*)mask)[idx] != 0);
}

__global__ __launch_bounds__(NT, 1) void crf_fused_kernel(
    const float* __restrict__ feats,      // (T, B, L)
    const float* __restrict__ trans,      // (L, L)
    const void*  __restrict__ candA,      // tags or mask
    const void*  __restrict__ candB,      // the other one
    float*       __restrict__ out)
{
    const int b    = blockIdx.x;
    const int tid  = threadIdx.x;
    const int j    = tid >> 1;    // output state 0..47
    const int h    = tid & 1;     // which half of the i-range
    const int w    = tid >> 5;    // warp id 0..2
    const int lane = tid & 31;

    __shared__ __align__(16) float s_u[2][LLAB];  // ping-pong partition (linear)
    __shared__ float s_gwarp[3];
    __shared__ float s_red[BB];
    __shared__ float s_gold;
    __shared__ int   s_len;
    __shared__ int   s_flags;
    __shared__ int   s_last;

    if (tid == 0) { s_len = 0; s_flags = 0; s_last = 0; }
    __syncthreads();

    // ---------------- buffer identification (one LDG round) ----------------
    if (tid < 64) {
        const unsigned* ua = (const unsigned*)candA;
        const unsigned* ub = (const unsigned*)candB;
        int f = 0;
        if (ua[tid] & 0xFEFEFEFEu)      f |= 1;   // A has a byte >= 2 -> A=tags
        if (ub[tid] & 0xFEFEFEFEu)      f |= 2;
        if (ua[2 * tid + 1] != 0)        f |= 4;   // A odd 32-bit words nonzero
        if (ub[2 * tid + 1] != 0)        f |= 8;
        if ((ua[0] & 0x0000FF00u) != 0)  f |= 16;  // A word0 byte1 (1B-mask sig)
        if ((ub[0] & 0x0000FF00u) != 0)  f |= 32;
        if (f) atomicOr(&s_flags, f);
    }
    __syncthreads();
    const int flags = s_flags;
    const int swap  = !(flags & 1);              // A has no byte>1 => A is mask
    const void* tags = swap ? candB : candA;
    const void* mask = swap ? candA : candB;
    const int is32 = swap ? ((flags >> 3) & 1) : ((flags >> 2) & 1);
    const int is8  = swap ? ((flags >> 4) & 1) : ((flags >> 5) & 1);

    // ---------------- gold path score (parallel over t) + length -----------
    {
        float gpart = 0.0f;
        int   lpart = 0;
        for (int t = tid; t < TT; t += NT) {
            if (get_mask(mask, b * TT + t, is8)) {
                lpart++;
                int tag  = get_tag(tags, b * TT + t, is32);
                int prev = (t == 0) ? START_TAG : get_tag(tags, b * TT + t - 1, is32);
                gpart += feats[t * FSTRIDE + b * LLAB + tag]
                       + trans[prev * LLAB + tag];
            }
        }
        #pragma unroll
        for (int off = 16; off > 0; off >>= 1)
            gpart += __shfl_xor_sync(0xffffffffu, gpart, off);  // fixed order
        if (lane == 0) s_gwarp[w] = gpart;
        atomicAdd(&s_len, lpart);   // integer: deterministic
    }

    // ---------------- per-thread E column slice (registers) ----------------
    float Ereg[24];
    #pragma unroll
    for (int r = 0; r < 24; ++r)
        Ereg[r] = expf(trans[(24 * h + r) * LLAB + j]);

    // ---------------- init: p_0 = f_0 + Tr[START][:] ------------------------
    const float* fb = feats + b * LLAB;
    float p00 = fb[0] + trans[START_TAG * LLAB + 0];
    float p0j = fb[j] + trans[START_TAG * LLAB + j];
    if (h == 0) s_u[0][j] = exp2f((p0j - p00) * L2E);
    float Cacc  = p00;    // log-offset, accumulated redundantly in all threads
    float Clog2 = 0.0f;

    __syncthreads();
    int len = s_len;                     // lengths in [256, 512]
    len = len < 1 ? 1 : (len > TT ? TT : len);

    if (tid == 0) {
        int endid = get_tag(tags, b * TT + len - 1, is32);
        s_gold = (s_gwarp[0] + s_gwarp[1] + s_gwarp[2])
               + trans[endid * LLAB + STOP_TAG];
    }

    // ---------------- forward recursion, distance-PFD feats prefetch --------
    float pfj[PFD], pf0[PFD];
    #pragma unroll
    for (int k = 0; k < PFD; ++k) {
        int tt = 1 + k; if (tt > len - 1) tt = len - 1;
        pfj[k] = fb[tt * FSTRIDE + j];
        pf0[k] = fb[tt * FSTRIDE];
    }

    const float* uin  = s_u[0];
    float*       uout = (float*)s_u[1];

    for (int tb = 1; tb < len; tb += PFD) {
        #pragma unroll
        for (int k = 0; k < PFD; ++k) {
            const int t = tb + k;
            if (t >= len) break;              // uniform across block: safe w/ bar

            int tp = t + PFD; if (tp > len - 1) tp = len - 1;
            float nfj = fb[tp * FSTRIDE + j];
            float nf0 = fb[tp * FSTRIDE];

            float fj = pfj[k], f0 = pf0[k];
            float e  = exp2f((fj - f0) * L2E);   // MUFU hidden under barrier

            __syncthreads();                     // uin fully written
            float u0 = uin[0];
            float ru = __fdividef(1.0f, u0);     // MUFU.RCP, hidden under dot

            float a0 = 0.f, a1 = 0.f, a2 = 0.f, a3 = 0.f;
            const float4* u4 = reinterpret_cast<const float4*>(uin + 24 * h);
            #pragma unroll
            for (int r = 0; r < 6; ++r) {
                float4 v = u4[r];
                a0 = fmaf(v.x, Ereg[4 * r + 0], a0);
                a1 = fmaf(v.y, Ereg[4 * r + 1], a1);
                a2 = fmaf(v.z, Ereg[4 * r + 2], a2);
                a3 = fmaf(v.w, Ereg[4 * r + 3], a3);
            }
            float s = (a0 + a1) + (a2 + a3);
            s += __shfl_xor_sync(0xffffffffu, s, 1);   // combine two halves

            float er   = e * ru;                  // off critical path
            float unew = s * er;                  // one FMUL after shfl
            if (h == 0) uout[j] = unew;

            Clog2 += log2f(u0);
            Cacc  += f0;
            pfj[k] = nfj; pf0[k] = nf0;

            const float* tmp = uin; uin = uout; uout = (float*)tmp;
        }
    }

    __syncthreads();

    // ---------------- final transition to STOP + partial write --------------
    if (j == STOP_TAG && h == 0) {           // tid 94 (lane 30, warp 2)
        float a0 = 0.f, a1 = 0.f, a2 = 0.f, a3 = 0.f;
        const float4* u4 = reinterpret_cast<const float4*>(uin);
        #pragma unroll
        for (int r = 0; r < 6; ++r) {
            float4 v = u4[r];
            a0 = fmaf(v.x, Ereg[4 * r + 0], a0);
            a1 = fmaf(v.y, Ereg[4 * r + 1], a1);
            a2 = fmaf(v.z, Ereg[4 * r + 2], a2);
            a3 = fmaf(v.w, Ereg[4 * r + 3], a3);
        }
        // other half of the dot (i = 24..47) done locally: load directly
        #pragma unroll
        for (int r = 0; r < 6; ++r) {
            float4 v = reinterpret_cast<const float4*>(uin + 24)[r];
            // E rows 24..47 for column STOP: recompute from trans (off path)
            a0 = fmaf(v.x, expf(trans[(24 + 4 * r + 0) * LLAB + STOP_TAG]), a0);
            a1 = fmaf(v.y, expf(trans[(24 + 4 * r + 1) * LLAB + STOP_TAG]), a1);
            a2 = fmaf(v.z, expf(trans[(24 + 4 * r + 2) * LLAB + STOP_TAG]), a2);
            a3 = fmaf(v.w, expf(trans[(24 + 4 * r + 3) * LLAB + STOP_TAG]), a3);
        }
        float s = (a0 + a1) + (a2 + a3);
        float fwd = Cacc + (Clog2 + log2f(s)) * LN2f;
        g_partial[b] = fwd - s_gold;
        __threadfence();
        if (atomicInc(&g_done, BB - 1) == BB - 1) s_last = 1;
    }
    __syncthreads();

    // ---------------- last block: deterministic fixed-order reduction -------
    if (s_last) {
        if (tid < BB) s_red[tid] = __ldcg(&g_partial[tid]);
        __syncthreads();
        if (tid == 0) {
            float v0 = 0.f, v1 = 0.f, v2 = 0.f, v3 = 0.f;
            #pragma unroll
            for (int i = 0; i < BB; i += 4) {
                v0 += s_red[i + 0];
                v1 += s_red[i + 1];
                v2 += s_red[i + 2];
                v3 += s_red[i + 3];
            }
            out[0] = (v0 + v1) + (v2 + v3);
        }
    }
}

extern "C" void kernel_launch(void* const* d_in, const int* in_sizes, int n_in,
                              void* d_out, int out_size) {
    // Resolve inputs by element count (order-independent).
    const float* feats = nullptr;
    const float* trans = nullptr;
    const void*  candA = nullptr;
    const void*  candB = nullptr;
    for (int i = 0; i < n_in; ++i) {
        long long c = in_sizes[i];
        if      (c == (long long)TT * BB * LLAB) feats = (const float*)d_in[i];
        else if (c == (long long)LLAB * LLAB)    trans = (const float*)d_in[i];
        else if (!candA)                         candA = d_in[i];
        else                                     candB = d_in[i];
    }

    crf_fused_kernel<<<BB, NT>>>(feats, trans, candA, candB, (float*)d_out);
}

// round 5
// speedup vs baseline: 1.6856x; 1.6856x over previous
#include <cuda_runtime.h>

// CRF negative log-likelihood, T=512 B=64 L=48, START=46, STOP=47.
// Fused kernel: buffer detection + gold score + forward recursion +
// last-block deterministic reduction.
//
// Forward recursion in linear space, rescaled every RESC steps by u[0]:
//   s_j  = sum_i u[i] * E[i][j],   E = exp(Tr)   (packed f32x2 FMAs)
//   u'[j]= s_j * exp(f_t[j]-f_t[0])   [ / u[0] on rescale steps ]
//   C accumulates f_t[0] and ln of the rescale factors.

#define TT 512
#define BB 64
#define LLAB 48
#define START_TAG 46
#define STOP_TAG 47
#define NT 96
#define RESC 8
#define L2E 1.4426950408889634f
#define LN2f 0.6931471805599453f
#define FSTRIDE (BB * LLAB)   // 3072 floats per time step

__device__ float        g_partial[BB];
__device__ unsigned int g_done;       // wraps 0..63 -> self-resetting

__device__ __forceinline__ int get_tag(const void* tags, int idx, int is32) {
    int v = is32 ? ((const int*)tags)[idx]
                 : (int)((const long long*)tags)[idx];
    return v < 0 ? 0 : (v > 47 ? 47 : v);
}
__device__ __forceinline__ int get_mask(const void* mask, int idx, int is8) {
    return is8 ? (int)((const unsigned char*)mask)[idx]
               : (((const int*)mask)[idx] != 0);
}

__global__ __launch_bounds__(NT, 1) void crf_fused_kernel(
    const float* __restrict__ feats,      // (T, B, L)
    const float* __restrict__ trans,      // (L, L)
    const void*  __restrict__ candA,
    const void*  __restrict__ candB,
    float*       __restrict__ out)
{
    const int b    = blockIdx.x;
    const int tid  = threadIdx.x;
    const int j    = tid >> 1;    // output state 0..47
    const int h    = tid & 1;     // half of the i-range
    const int w    = tid >> 5;
    const int lane = tid & 31;

    __shared__ __align__(16) float s_u[2][LLAB];
    __shared__ float s_gwarp[3];
    __shared__ float s_red[BB];
    __shared__ float s_gold;
    __shared__ int   s_len;
    __shared__ int   s_flags;
    __shared__ int   s_last;

    if (tid == 0) { s_len = 0; s_flags = 0; s_last = 0; }
    __syncthreads();

    // ---------------- buffer identification (one LDG round) ----------------
    if (tid < 64) {
        const unsigned* ua = (const unsigned*)candA;
        const unsigned* ub = (const unsigned*)candB;
        int f = 0;
        if (ua[tid] & 0xFEFEFEFEu)       f |= 1;   // A has byte >= 2 -> A=tags
        if (ub[tid] & 0xFEFEFEFEu)       f |= 2;
        if (ua[2 * tid + 1] != 0)        f |= 4;   // A odd words nonzero -> i32
        if (ub[2 * tid + 1] != 0)        f |= 8;
        if ((ua[0] & 0x0000FF00u) != 0)  f |= 16;  // 1-byte mask signature
        if ((ub[0] & 0x0000FF00u) != 0)  f |= 32;
        if (f) atomicOr(&s_flags, f);
    }
    __syncthreads();
    const int flags = s_flags;
    const int swap  = !(flags & 1);
    const void* tags = swap ? candB : candA;
    const void* mask = swap ? candA : candB;
    const int is32 = swap ? ((flags >> 3) & 1) : ((flags >> 2) & 1);
    const int is8  = swap ? ((flags >> 4) & 1) : ((flags >> 5) & 1);

    // ---------------- gold path score + length -----------------------------
    {
        float gpart = 0.0f;
        int   lpart = 0;
        for (int t = tid; t < TT; t += NT) {
            if (get_mask(mask, b * TT + t, is8)) {
                lpart++;
                int tag  = get_tag(tags, b * TT + t, is32);
                int prev = (t == 0) ? START_TAG : get_tag(tags, b * TT + t - 1, is32);
                gpart += feats[t * FSTRIDE + b * LLAB + tag]
                       + trans[prev * LLAB + tag];
            }
        }
        #pragma unroll
        for (int off = 16; off > 0; off >>= 1)
            gpart += __shfl_xor_sync(0xffffffffu, gpart, off);  // fixed order
        if (lane == 0) s_gwarp[w] = gpart;
        atomicAdd(&s_len, lpart);
    }

    // ------------- per-thread packed-E column slice (12 x f32x2) -----------
    unsigned long long Epk[12];
    #pragma unroll
    for (int r = 0; r < 12; ++r) {
        float e0 = expf(trans[(24 * h + 2 * r)     * LLAB + j]);
        float e1 = expf(trans[(24 * h + 2 * r + 1) * LLAB + j]);
        unsigned long long pk;
        asm("mov.b64 %0, {%1, %2};" : "=l"(pk) : "f"(e0), "f"(e1));
        Epk[r] = pk;
    }

    // ---------------- init: p_0 = f_0 + Tr[START][:] ------------------------
    const float* fb = feats + b * LLAB;
    float p00 = fb[0] + trans[START_TAG * LLAB + 0];
    float p0j = fb[j] + trans[START_TAG * LLAB + j];
    if (h == 0) s_u[0][j] = exp2f((p0j - p00) * L2E);
    float Cacc  = p00;
    float Clog2 = 0.0f;

    __syncthreads();
    int len = s_len;
    len = len < 1 ? 1 : (len > TT ? TT : len);
    const int nsteps = len - 1;          // >= 255

    if (tid == 0) {
        int endid = get_tag(tags, b * TT + len - 1, is32);
        s_gold = (s_gwarp[0] + s_gwarp[1] + s_gwarp[2])
               + trans[endid * LLAB + STOP_TAG];
    }

    // ---------------- forward recursion --------------------------------------
    float pfj[2], pf0[2];
    {
        int t1 = 1 < nsteps ? 1 : nsteps;  if (t1 < 0) t1 = 0;
        int t2 = 2 < nsteps ? 2 : nsteps;  if (t2 < 0) t2 = 0;
        pfj[1] = fb[t1 * FSTRIDE + j];  pf0[1] = fb[t1 * FSTRIDE];
        pfj[0] = fb[t2 * FSTRIDE + j];  pf0[0] = fb[t2 * FSTRIDE];
    }

    const int npad = ((nsteps + RESC - 1) / RESC) * RESC;

    for (int tb = 1; tb <= npad; tb += RESC) {
        #pragma unroll
        for (int k = 0; k < RESC; ++k) {
            const int  t    = tb + k;
            const bool live = (t <= nsteps);          // uniform across block

            int tp = t + 2; if (tp > nsteps) tp = nsteps;
            float nfj = fb[tp * FSTRIDE + j];
            float nf0 = fb[tp * FSTRIDE];

            float fj = pfj[k & 1], f0 = pf0[k & 1];
            float e  = exp2f((fj - f0) * L2E);        // before bar: hidden

            __syncthreads();                          // u[(t-1)&1] complete
            const float* uin = s_u[(t - 1) & 1];

            float ru = 1.0f;
            if (k == 0) {                             // rescale step
                float u0 = uin[0];
                ru = __fdividef(1.0f, u0);
                if (live) Clog2 += log2f(u0);
            }
            if (live) Cacc += f0;

            unsigned long long acc0 = 0ULL, acc1 = 0ULL;   // packed (0,0)
            const ulonglong2* up =
                reinterpret_cast<const ulonglong2*>(uin + 24 * h);
            #pragma unroll
            for (int r = 0; r < 6; ++r) {
                ulonglong2 q = up[r];
                asm("fma.rn.f32x2 %0, %1, %2, %0;"
                    : "+l"(acc0) : "l"(q.x), "l"(Epk[2 * r]));
                asm("fma.rn.f32x2 %0, %1, %2, %0;"
                    : "+l"(acc1) : "l"(q.y), "l"(Epk[2 * r + 1]));
            }
            unsigned long long accs;
            asm("add.rn.f32x2 %0, %1, %2;" : "=l"(accs) : "l"(acc0), "l"(acc1));
            float slo, shi;
            asm("mov.b64 {%0, %1}, %2;" : "=f"(slo), "=f"(shi) : "l"(accs));
            float s = slo + shi;
            s += __shfl_xor_sync(0xffffffffu, s, 1);  // combine halves

            float unew = (k == 0) ? s * e * ru : s * e;
            if (h == 0 && live) s_u[t & 1][j] = unew;

            pfj[k & 1] = nfj; pf0[k & 1] = nf0;
        }
    }

    __syncthreads();

    // ---------------- final transition to STOP + partial write --------------
    if (tid == 94) {                 // (j=47, h=0)
        const float* uin = s_u[(len - 1) & 1];
        float a0 = 0.f, a1 = 0.f, a2 = 0.f, a3 = 0.f;
        #pragma unroll
        for (int i = 0; i < LLAB; i += 4) {
            a0 = fmaf(uin[i + 0], expf(trans[(i + 0) * LLAB + STOP_TAG]), a0);
            a1 = fmaf(uin[i + 1], expf(trans[(i + 1) * LLAB + STOP_TAG]), a1);
            a2 = fmaf(uin[i + 2], expf(trans[(i + 2) * LLAB + STOP_TAG]), a2);
            a3 = fmaf(uin[i + 3], expf(trans[(i + 3) * LLAB + STOP_TAG]), a3);
        }
        float s = (a0 + a1) + (a2 + a3);
        float fwd = Cacc + (Clog2 + log2f(s)) * LN2f;
        g_partial[b] = fwd - s_gold;
        __threadfence();
        if (atomicInc(&g_done, BB - 1) == BB - 1) s_last = 1;
    }
    __syncthreads();

    // ---------------- last block: deterministic fixed-order reduction -------
    if (s_last) {
        if (tid < BB) s_red[tid] = __ldcg(&g_partial[tid]);
        __syncthreads();
        if (tid == 0) {
            float v0 = 0.f, v1 = 0.f, v2 = 0.f, v3 = 0.f;
            #pragma unroll
            for (int i = 0; i < BB; i += 4) {
                v0 += s_red[i + 0];
                v1 += s_red[i + 1];
                v2 += s_red[i + 2];
                v3 += s_red[i + 3];
            }
            out[0] = (v0 + v1) + (v2 + v3);
        }
    }
}

extern "C" void kernel_launch(void* const* d_in, const int* in_sizes, int n_in,
                              void* d_out, int out_size) {
    const float* feats = nullptr;
    const float* trans = nullptr;
    const void*  candA = nullptr;
    const void*  candB = nullptr;
    for (int i = 0; i < n_in; ++i) {
        long long c = in_sizes[i];
        if      (c == (long long)TT * BB * LLAB) feats = (const float*)d_in[i];
        else if (c == (long long)LLAB * LLAB)    trans = (const float*)d_in[i];
        else if (!candA)                         candA = d_in[i];
        else                                     candB = d_in[i];
    }

    crf_fused_kernel<<<BB, NT>>>(feats, trans, candA, candB, (float*)d_out);
}